// round 9
// baseline (speedup 1.0000x reference)
#include <cuda_runtime.h>
#include <cuda_bf16.h>
#include <cstdint>

// ---------------- problem constants ----------------
#define DIN      1024
#define NPROJ    256
#define NC       64
#define NOUT     (NPROJ + NC)        // 320
#define TILE_M   64
#define KC       64                  // k per chunk
#define NKCH     (DIN / KC)          // 16 chunks
#define THREADS  256                 // main kernel: 8 warps = 2(M) x 4(N)
#define PREP_THREADS 512

// global B image: [chunk][n][k] bf16, row n = 128B per chunk
#define B_CHUNK_BYTES (NOUT * KC * 2)    // 40960

// smem row stride: 128B data + 16B pad -> conflict-free ldmatrix
#define ROWB 144
#define A_STAGE (TILE_M * ROWB)          // 9216
#define B_STAGE (NOUT * ROWB)            // 46080

// smem layout (bytes)
#define SM_SSQ    0                      // 64 f32
#define SM_MPROJ  256                    // 320 f32 (cols >=256 are 0)
#define SM_MPP    1536                   // 64 f32
#define SM_PN2    1792                   // 64 f32
#define SM_A      2048                   // 2 stages
#define SM_B      (SM_A + 2 * A_STAGE)   // 20480
#define SM_TOTAL  (SM_B + 2 * B_STAGE)   // 112640  (x2 CTAs = 225,280 <= 228KB)

// prep smem: staging 2*32*257 floats (== 64*257 for the mean2 tail) + 2048 scratch
#define PREP_STAGE_F  (2 * 32 * 257)     // 16448 floats
#define PREP_SMEM_BYTES ((PREP_STAGE_F + 2048) * 4)   // 73984 B

// ---------------- device-global scratch ----------------
__device__ __align__(128) unsigned char g_Bimg[NKCH * B_CHUNK_BYTES];  // 640 KB
__device__ float g_part[32 * NPROJ];
__device__ float g_mproj[NPROJ];
__device__ float g_mpP[NC];
__device__ float g_pn2[NC];
__device__ int   g_ctr = 0;

// ---------------- helpers ----------------
__device__ __forceinline__ uint32_t smem_u32(const void* p) {
    uint32_t a;
    asm("{ .reg .u64 t; cvta.to.shared.u64 t, %1; cvt.u32.u64 %0, t; }" : "=r"(a) : "l"(p));
    return a;
}

// low 16 bits = bf16(lo), high 16 = bf16(hi)
__device__ __forceinline__ uint32_t pack_bf(float lo, float hi) {
    uint32_t r;
    asm("cvt.rn.satfinite.bf16x2.f32 %0, %1, %2;" : "=r"(r) : "f"(hi), "f"(lo));
    return r;
}

#define LDSM_X4(r0, r1, r2, r3, addr) \
    asm volatile("ldmatrix.sync.aligned.m8n8.x4.shared.b16 {%0,%1,%2,%3}, [%4];" \
                 : "=r"(r0), "=r"(r1), "=r"(r2), "=r"(r3) : "r"(addr))

__device__ __forceinline__ void mma16816(float* d, const uint32_t* a, uint32_t b0, uint32_t b1) {
    asm volatile(
        "mma.sync.aligned.m16n8k16.row.col.f32.bf16.bf16.f32 "
        "{%0,%1,%2,%3}, {%4,%5,%6,%7}, {%8,%9}, {%0,%1,%2,%3};"
        : "+f"(d[0]), "+f"(d[1]), "+f"(d[2]), "+f"(d[3])
        : "r"(a[0]), "r"(a[1]), "r"(a[2]), "r"(a[3]), "r"(b0), "r"(b1));
}

#define CP_ASYNC16(dst, src) \
    asm volatile("cp.async.cg.shared.global [%0], [%1], 16;" :: "r"(dst), "l"(src) : "memory")
#define CP_COMMIT() asm volatile("cp.async.commit_group;" ::: "memory")

// ---------------- prep kernel: B image [W | W@P^T], mean@W, mproj@P^T, |P|^2 ----------------
// grid = 64 blocks x 512 threads. Block (kc32 = bid>>1, cg = bid&1):
//   stages W rows [kc32*32,+32) and P rows [cg*32,+32) in smem (stride 257).
//   tid<256 & cg==0: W-part of image. tid>=256 & cg==1: 32-k partial of mean@W.
//   T-part: j-loop split in half across tid>>8; partials combined via smem.
//   Last block to finish (atomic counter) computes mproj reduce + mproj@P^T + |P|^2.
__global__ void prep_img(const float* __restrict__ W, const float* __restrict__ P,
                         const float* __restrict__ mean) {
    extern __shared__ float sprep[];
    float* Wc = sprep;                   // [32][257]
    float* Pc = sprep + 32 * 257;        // [32][257]
    float* sT = sprep + PREP_STAGE_F;    // [2][32][32] T partials (2048 floats)
    __shared__ int s_last;
    const int tid = threadIdx.x;
    const int kc32 = blockIdx.x >> 1;
    const int cg = blockIdx.x & 1;
    const int k0 = kc32 * 32, c0 = cg * 32;
    const int kc64 = kc32 >> 1, kbase = (kc32 & 1) * 32;
    unsigned char* cbase = g_Bimg + (size_t)kc64 * B_CHUNK_BYTES;

    for (int idx = tid; idx < 2048; idx += PREP_THREADS) {
        const int r = idx >> 6, j4 = (idx & 63) * 4;
        float4 w = *(const float4*)(W + (size_t)(k0 + r) * NPROJ + j4);
        Wc[r * 257 + j4 + 0] = w.x; Wc[r * 257 + j4 + 1] = w.y;
        Wc[r * 257 + j4 + 2] = w.z; Wc[r * 257 + j4 + 3] = w.w;
        float4 p = *(const float4*)(P + (size_t)(c0 + r) * NPROJ + j4);
        Pc[r * 257 + j4 + 0] = p.x; Pc[r * 257 + j4 + 1] = p.y;
        Pc[r * 257 + j4 + 2] = p.z; Pc[r * 257 + j4 + 3] = p.w;
    }
    __syncthreads();

    if (cg == 0) {
        if (tid < 256) {
            // W-part: thread = column n, pack this block's 32 k's
            unsigned char* dst = cbase + tid * 128 + kbase * 2;
#pragma unroll
            for (int q = 0; q < 4; q++) {
                uint4 u;
                u.x = pack_bf(Wc[(q * 8 + 0) * 257 + tid], Wc[(q * 8 + 1) * 257 + tid]);
                u.y = pack_bf(Wc[(q * 8 + 2) * 257 + tid], Wc[(q * 8 + 3) * 257 + tid]);
                u.z = pack_bf(Wc[(q * 8 + 4) * 257 + tid], Wc[(q * 8 + 5) * 257 + tid]);
                u.w = pack_bf(Wc[(q * 8 + 6) * 257 + tid], Wc[(q * 8 + 7) * 257 + tid]);
                *(uint4*)(dst + q * 16) = u;
            }
        }
    } else {
        if (tid >= 256) {
            // mean@W partial over this k-block: thread = column n
            const int n = tid - 256;
            float a = 0.f;
#pragma unroll 8
            for (int r = 0; r < 32; r++)
                a = fmaf(mean[k0 + r], Wc[r * 257 + n], a);
            g_part[kc32 * NPROJ + n] = a;
        }
    }

    // T-part: thread -> (k = tid&31, c-group cq = (tid>>5)&7, j-half jh = tid>>8)
    {
        const int kl = tid & 31, cq = (tid >> 5) & 7, jh = tid >> 8;
        float acc[4] = {0.f, 0.f, 0.f, 0.f};
        const float* wrow = Wc + kl * 257 + jh * 128;
        const float* prow = Pc + jh * 128;
#pragma unroll 4
        for (int j = 0; j < 128; j++) {
            const float w = wrow[j];
#pragma unroll
            for (int i = 0; i < 4; i++)
                acc[i] = fmaf(w, prow[(cq * 4 + i) * 257 + j], acc[i]);
        }
#pragma unroll
        for (int i = 0; i < 4; i++)
            sT[jh * 1024 + kl * 32 + cq * 4 + i] = acc[i];
    }
    __syncthreads();

    if (tid < 256) {
        const int kl = tid & 31, cq = tid >> 5;
#pragma unroll
        for (int i = 0; i < 4; i++) {
            const int c = c0 + cq * 4 + i;
            const float v = sT[kl * 32 + cq * 4 + i] + sT[1024 + kl * 32 + cq * 4 + i];
            *(__nv_bfloat16*)(cbase + (NPROJ + c) * 128 + (kbase + kl) * 2) =
                __float2bfloat16_rn(v);
        }
    }

    // ---- last block: mproj reduce + mproj@P^T + |P|^2 ----
    __syncthreads();
    if (tid == 0) {
        __threadfence();
        s_last = (atomicAdd(&g_ctr, 1) == 63);
    }
    __syncthreads();
    if (!s_last) return;

    float* sP  = sprep;          // [64][257] (reuses staging region exactly)
    float* sm  = sT;             // [256] mproj
    float* smp = sT + 256;       // [8][64]
    float* sp2 = sT + 768;       // [8][64]

    for (int idx = tid; idx < 4096; idx += PREP_THREADS) {
        const int r = idx >> 6, j4 = (idx & 63) * 4;
        float4 p = *(const float4*)(P + (size_t)r * NPROJ + j4);
        sP[r * 257 + j4 + 0] = p.x; sP[r * 257 + j4 + 1] = p.y;
        sP[r * 257 + j4 + 2] = p.z; sP[r * 257 + j4 + 3] = p.w;
    }
    if (tid < 256) {
        float a = 0.f;
#pragma unroll 8
        for (int b = 0; b < 32; b++) a += g_part[b * NPROJ + tid];
        g_mproj[tid] = a;
        sm[tid] = a;
    }
    __syncthreads();

    // dots: thread -> (c = tid&63, eighth q = tid>>6); 32-j partials
    {
        const int c = tid & 63, q = tid >> 6;
        const float* pr = sP + c * 257 + q * 32;
        const float* mr = sm + q * 32;
        float mp = 0.f, p2 = 0.f;
#pragma unroll 8
        for (int j = 0; j < 32; j++) {
            const float pv = pr[j];
            mp = fmaf(mr[j], pv, mp);
            p2 = fmaf(pv, pv, p2);
        }
        smp[q * 64 + c] = mp;
        sp2[q * 64 + c] = p2;
    }
    __syncthreads();

    if (tid < NC) {
        float mp = 0.f, p2 = 0.f;
#pragma unroll
        for (int q = 0; q < 8; q++) { mp += smp[q * 64 + tid]; p2 += sp2[q * 64 + tid]; }
        g_mpP[tid] = mp;
        g_pn2[tid] = p2;
    }
    if (tid == 0) g_ctr = 0;   // reset for next graph replay
}

// ---------------- main fused GEMM + epilogue ----------------
// grid = nrows/64 CTAs of 256 threads; 2 CTAs/SM. 8 warps = 2(M) x 4(N),
// warp tile 32x80. 16 K-chunks of 64; one barrier per chunk; B double-buffered
// cp.async (issued BEFORE the wait -> wait_group 1 never blocks on the new
// group); A double-buffered through registers; A fragments software-pipelined
// across ks; B fragments prefetched one p-step ahead.
__global__ __launch_bounds__(THREADS, 2)
void proto_main(const float* __restrict__ X, float* __restrict__ out) {
    extern __shared__ char smem[];
    float* s_ssq   = (float*)(smem + SM_SSQ);
    float* s_mproj = (float*)(smem + SM_MPROJ);
    float* s_mpp   = (float*)(smem + SM_MPP);
    float* s_pn2   = (float*)(smem + SM_PN2);
    const uint32_t sbase = smem_u32(smem);
    const uint32_t sA = sbase + SM_A;
    const uint32_t sB = sbase + SM_B;

    const int tid = threadIdx.x;
    const int lane = tid & 31, wid = tid >> 5;
    const int wm = wid >> 2, wn = wid & 3;
    const int m0 = blockIdx.x * TILE_M;

    for (int i = tid; i < NOUT; i += THREADS)
        s_mproj[i] = (i < NPROJ) ? g_mproj[i] : 0.f;
    if (tid < NC) { s_mpp[tid] = g_mpP[tid]; s_pn2[tid] = g_pn2[tid]; }
    if (tid < TILE_M) s_ssq[tid] = 0.f;

    // A mapping: thread -> (row = tid/4, quarter = tid%4); each thread owns
    // 16 consecutive k of its row per chunk (64B src fp32 -> 32B bf16).
    const int arow = tid >> 2, aq = tid & 3;
    const float* xptr = X + (size_t)(m0 + arow) * DIN + aq * 16;
    char* aStsBase = smem + SM_A + arow * ROWB + aq * 32;

    float acc[2][5][2][4];
#pragma unroll
    for (int mt = 0; mt < 2; mt++)
#pragma unroll
        for (int p = 0; p < 5; p++)
#pragma unroll
            for (int nt = 0; nt < 2; nt++)
#pragma unroll
                for (int q = 0; q < 4; q++) acc[mt][p][nt][q] = 0.f;

    auto loadA = [&](int kc, uint4* dst) {
#pragma unroll
        for (int h = 0; h < 2; h++) {
            float4 v0 = *(const float4*)(xptr + kc * KC + h * 8);
            float4 v1 = *(const float4*)(xptr + kc * KC + h * 8 + 4);
            dst[h].x = pack_bf(v0.x, v0.y);
            dst[h].y = pack_bf(v0.z, v0.w);
            dst[h].z = pack_bf(v1.x, v1.y);
            dst[h].w = pack_bf(v1.z, v1.w);
        }
    };
    auto issueB = [&](int kc, int st) {
        const char* src = (const char*)g_Bimg + (size_t)kc * B_CHUNK_BYTES;
        const uint32_t dstb = sB + st * B_STAGE;
#pragma unroll
        for (int it = 0; it < 10; it++) {
            const int i = tid + it * THREADS;
            const int n = i >> 3, ch = i & 7;
            CP_ASYNC16(dstb + n * ROWB + ch * 16, src + n * 128 + ch * 16);
        }
        CP_COMMIT();
    };

    // ---- prologue ----
    issueB(0, 0);
    uint4 aCur[2], aNxt[2];
    loadA(0, aCur);

    // ldmatrix address invariants
    const uint32_t aRow = wm * 32 + (lane & 15);
    const uint32_t aColHalf = (lane >> 4) * 16;
    const uint32_t bRowOff = (lane & 7) + ((lane >> 4) & 1) * 8;
    const uint32_t bColHalf = ((lane >> 3) & 1) * 16;

    for (int kc = 0; kc < NKCH; kc++) {
        const int st = kc & 1;
        *(uint4*)(aStsBase + st * A_STAGE)      = aCur[0];
        *(uint4*)(aStsBase + st * A_STAGE + 16) = aCur[1];
        if (kc < NKCH - 1) loadA(kc + 1, aNxt);

        // issue next B first so wait_group 1 drains only the old group
        if (kc < NKCH - 1) {
            issueB(kc + 1, st ^ 1);
            asm volatile("cp.async.wait_group 1;" ::: "memory");
        } else {
            asm volatile("cp.async.wait_group 0;" ::: "memory");
        }
        __syncthreads();

        const uint32_t aBase = sA + st * A_STAGE;
        const uint32_t bBase = sB + st * B_STAGE;

        // A fragments software-pipelined across ks
        uint32_t afq[2][4], afn[2][4];
#pragma unroll
        for (int mt = 0; mt < 2; mt++) {
            const uint32_t addr = aBase + (aRow + mt * 16) * ROWB + aColHalf;
            LDSM_X4(afq[mt][0], afq[mt][1], afq[mt][2], afq[mt][3], addr);
        }
#pragma unroll
        for (int ks = 0; ks < 4; ks++) {
            if (ks < 3) {
#pragma unroll
                for (int mt = 0; mt < 2; mt++) {
                    const uint32_t addr =
                        aBase + (aRow + mt * 16) * ROWB + (ks + 1) * 32 + aColHalf;
                    LDSM_X4(afn[mt][0], afn[mt][1], afn[mt][2], afn[mt][3], addr);
                }
            }
            const uint32_t bks = bBase + ks * 32 + bColHalf + bRowOff * ROWB + wn * (80 * ROWB);
            uint32_t bq[4], bn[4];
            LDSM_X4(bq[0], bq[1], bq[2], bq[3], bks);
#pragma unroll
            for (int p = 0; p < 5; p++) {
                if (p < 4) LDSM_X4(bn[0], bn[1], bn[2], bn[3], bks + (p + 1) * (16 * ROWB));
#pragma unroll
                for (int mt = 0; mt < 2; mt++) {
                    mma16816(acc[mt][p][0], afq[mt], bq[0], bq[1]);
                    mma16816(acc[mt][p][1], afq[mt], bq[2], bq[3]);
                }
                bq[0] = bn[0]; bq[1] = bn[1]; bq[2] = bn[2]; bq[3] = bn[3];
            }
#pragma unroll
            for (int mt = 0; mt < 2; mt++)
#pragma unroll
                for (int q = 0; q < 4; q++) afq[mt][q] = afn[mt][q];
        }
        aCur[0] = aNxt[0]; aCur[1] = aNxt[1];
    }

    // ---------------- epilogue ----------------
    // 1) partial sumsq of centered Z per row (cols >= 256 gated to 0)
    float pss[2][2] = {{0.f, 0.f}, {0.f, 0.f}};
#pragma unroll
    for (int mt = 0; mt < 2; mt++)
#pragma unroll
        for (int p = 0; p < 5; p++)
#pragma unroll
            for (int nt = 0; nt < 2; nt++) {
                const int col = wn * 80 + p * 16 + nt * 8 + (lane & 3) * 2;
                const float g = (col < NPROJ) ? 1.f : 0.f;
                const float mv0 = s_mproj[col], mv1 = s_mproj[col + 1];
                float v0 = acc[mt][p][nt][0] - mv0;
                float v1 = acc[mt][p][nt][1] - mv1;
                float v2 = acc[mt][p][nt][2] - mv0;
                float v3 = acc[mt][p][nt][3] - mv1;
                pss[mt][0] += g * fmaf(v0, v0, v1 * v1);
                pss[mt][1] += g * fmaf(v2, v2, v3 * v3);
            }
#pragma unroll
    for (int mt = 0; mt < 2; mt++)
#pragma unroll
        for (int rh = 0; rh < 2; rh++) {
            float v = pss[mt][rh];
            v += __shfl_xor_sync(0xFFFFFFFFu, v, 1);
            v += __shfl_xor_sync(0xFFFFFFFFu, v, 2);
            if ((lane & 3) == 0)
                atomicAdd(&s_ssq[wm * 32 + mt * 16 + rh * 8 + (lane >> 2)], v);
        }
    __syncthreads();

    // 2) scores: wn==3 warps hold all T columns (256..319)
    if (wn == 3) {
#pragma unroll
        for (int mt = 0; mt < 2; mt++) {
            const int rbase = wm * 32 + mt * 16 + (lane >> 2);
            float rn[2];
#pragma unroll
            for (int rh = 0; rh < 2; rh++) {
                const float ss = s_ssq[rbase + rh * 8];
                rn[rh] = 1.f / fmaxf(sqrtf(ss), 1e-12f);
            }
#pragma unroll
            for (int p = 1; p < 5; p++)
#pragma unroll
                for (int nt = 0; nt < 2; nt++) {
                    const int c = p * 16 + nt * 8 + (lane & 3) * 2 - 16;  // 0..62
                    const float mp0 = s_mpp[c], mp1 = s_mpp[c + 1];
                    const float pn0 = s_pn2[c], pn1 = s_pn2[c + 1];
#pragma unroll
                    for (int rh = 0; rh < 2; rh++) {
                        const float s0 = (acc[mt][p][nt][rh * 2 + 0] - mp0) * rn[rh];
                        const float s1 = (acc[mt][p][nt][rh * 2 + 1] - mp1) * rn[rh];
                        float2 o;
                        o.x = -sqrtf(fmaxf(fmaf(-2.f, s0, 1.f + pn0), 0.f));
                        o.y = -sqrtf(fmaxf(fmaf(-2.f, s1, 1.f + pn1), 0.f));
                        const int row = m0 + rbase + rh * 8;
                        *(float2*)(out + (size_t)row * NC + c) = o;
                    }
                }
        }
    }
}

// ---------------- launch ----------------
extern "C" void kernel_launch(void* const* d_in, const int* in_sizes, int n_in,
                              void* d_out, int out_size) {
    const float* X    = (const float*)d_in[0];   // [8,2048,1024]
    const float* P    = (const float*)d_in[1];   // [64,256]
    const float* mean = (const float*)d_in[2];   // [1024]
    const float* W    = (const float*)d_in[3];   // [1024,256]
    float* out = (float*)d_out;                  // [8,2048,64]

    const int nrows = in_sizes[0] / DIN;         // 16384

    cudaFuncSetAttribute(proto_main, cudaFuncAttributeMaxDynamicSharedMemorySize, SM_TOTAL);
    cudaFuncSetAttribute(prep_img, cudaFuncAttributeMaxDynamicSharedMemorySize, PREP_SMEM_BYTES);

    prep_img<<<64, PREP_THREADS, PREP_SMEM_BYTES>>>(W, P, mean);
    proto_main<<<nrows / TILE_M, THREADS, SM_TOTAL>>>(X, out);
}

// round 14
// speedup vs baseline: 1.0714x; 1.0714x over previous
#include <cuda_runtime.h>
#include <cuda_bf16.h>
#include <cstdint>

// ---------------- problem constants ----------------
#define DIN      1024
#define NPROJ    256
#define NC       64
#define NOUT     (NPROJ + NC)        // 320
#define TILE_M   64
#define KC       64                  // k per chunk
#define NKCH     (DIN / KC)          // 16 chunks
#define THREADS  256                 // main kernel: 8 warps = 2(M) x 4(N)
#define PREP_THREADS 512

// global B image: [chunk][n][k] bf16, row n = 128B per chunk
#define B_CHUNK_BYTES (NOUT * KC * 2)    // 40960

// smem row stride: 128B data + 16B pad -> conflict-free ldmatrix
#define ROWB 144
#define A_STAGE (TILE_M * ROWB)          // 9216
#define B_STAGE (NOUT * ROWB)            // 46080

// smem layout (bytes)
#define SM_SSQ    0                      // 64 f32
#define SM_MPROJ  256                    // 320 f32 (cols >=256 are 0)
#define SM_MPP    1536                   // 64 f32
#define SM_PN2    1792                   // 64 f32
#define SM_A      2048                   // 2 stages
#define SM_B      (SM_A + 2 * A_STAGE)   // 20480
#define SM_TOTAL  (SM_B + 2 * B_STAGE)   // 112640  (x2 CTAs = 225,280 <= 228KB)

// prep smem: staging 2*32*257 floats (== 64*257 for the mean2 tail) + 2048 scratch
#define PREP_STAGE_F  (2 * 32 * 257)     // 16448 floats
#define PREP_SMEM_BYTES ((PREP_STAGE_F + 2048) * 4)   // 73984 B

// ---------------- device-global scratch ----------------
__device__ __align__(128) unsigned char g_Bimg[NKCH * B_CHUNK_BYTES];  // 640 KB
__device__ float g_part[32 * NPROJ];
__device__ float g_mproj[NPROJ];
__device__ float g_mpP[NC];
__device__ float g_pn2[NC];
__device__ int   g_ctr = 0;

// ---------------- helpers ----------------
__device__ __forceinline__ uint32_t smem_u32(const void* p) {
    uint32_t a;
    asm("{ .reg .u64 t; cvta.to.shared.u64 t, %1; cvt.u32.u64 %0, t; }" : "=r"(a) : "l"(p));
    return a;
}

// low 16 bits = bf16(lo), high 16 = bf16(hi)
__device__ __forceinline__ uint32_t pack_bf(float lo, float hi) {
    uint32_t r;
    asm("cvt.rn.satfinite.bf16x2.f32 %0, %1, %2;" : "=r"(r) : "f"(hi), "f"(lo));
    return r;
}

#define LDSM_X4(r0, r1, r2, r3, addr) \
    asm volatile("ldmatrix.sync.aligned.m8n8.x4.shared.b16 {%0,%1,%2,%3}, [%4];" \
                 : "=r"(r0), "=r"(r1), "=r"(r2), "=r"(r3) : "r"(addr))

__device__ __forceinline__ void mma16816(float* d, const uint32_t* a, uint32_t b0, uint32_t b1) {
    asm volatile(
        "mma.sync.aligned.m16n8k16.row.col.f32.bf16.bf16.f32 "
        "{%0,%1,%2,%3}, {%4,%5,%6,%7}, {%8,%9}, {%0,%1,%2,%3};"
        : "+f"(d[0]), "+f"(d[1]), "+f"(d[2]), "+f"(d[3])
        : "r"(a[0]), "r"(a[1]), "r"(a[2]), "r"(a[3]), "r"(b0), "r"(b1));
}

#define CP_ASYNC16(dst, src) \
    asm volatile("cp.async.cg.shared.global [%0], [%1], 16;" :: "r"(dst), "l"(src) : "memory")
#define CP_COMMIT() asm volatile("cp.async.commit_group;" ::: "memory")

// ---------------- prep kernel: B image [W | W@P^T], mean@W, mproj@P^T, |P|^2 ----------------
// grid = 64 blocks x 512 threads. Block (kc32 = bid>>1, cg = bid&1):
//   stages W rows [kc32*32,+32) and P rows [cg*32,+32) in smem (stride 257).
//   tid<256 & cg==0: W-part of image. tid>=256 & cg==1: 32-k partial of mean@W.
//   T-part: j-loop split in half across tid>>8; partials combined via smem.
//   Last block to finish (atomic counter) computes mproj reduce + mproj@P^T + |P|^2.
__global__ void prep_img(const float* __restrict__ W, const float* __restrict__ P,
                         const float* __restrict__ mean) {
    extern __shared__ float sprep[];
    float* Wc = sprep;                   // [32][257]
    float* Pc = sprep + 32 * 257;        // [32][257]
    float* sT = sprep + PREP_STAGE_F;    // [2][32][32] T partials (2048 floats)
    __shared__ int s_last;
    const int tid = threadIdx.x;
    const int kc32 = blockIdx.x >> 1;
    const int cg = blockIdx.x & 1;
    const int k0 = kc32 * 32, c0 = cg * 32;
    const int kc64 = kc32 >> 1, kbase = (kc32 & 1) * 32;
    unsigned char* cbase = g_Bimg + (size_t)kc64 * B_CHUNK_BYTES;

    for (int idx = tid; idx < 2048; idx += PREP_THREADS) {
        const int r = idx >> 6, j4 = (idx & 63) * 4;
        float4 w = *(const float4*)(W + (size_t)(k0 + r) * NPROJ + j4);
        Wc[r * 257 + j4 + 0] = w.x; Wc[r * 257 + j4 + 1] = w.y;
        Wc[r * 257 + j4 + 2] = w.z; Wc[r * 257 + j4 + 3] = w.w;
        float4 p = *(const float4*)(P + (size_t)(c0 + r) * NPROJ + j4);
        Pc[r * 257 + j4 + 0] = p.x; Pc[r * 257 + j4 + 1] = p.y;
        Pc[r * 257 + j4 + 2] = p.z; Pc[r * 257 + j4 + 3] = p.w;
    }
    __syncthreads();

    if (cg == 0) {
        if (tid < 256) {
            // W-part: thread = column n, pack this block's 32 k's
            unsigned char* dst = cbase + tid * 128 + kbase * 2;
#pragma unroll
            for (int q = 0; q < 4; q++) {
                uint4 u;
                u.x = pack_bf(Wc[(q * 8 + 0) * 257 + tid], Wc[(q * 8 + 1) * 257 + tid]);
                u.y = pack_bf(Wc[(q * 8 + 2) * 257 + tid], Wc[(q * 8 + 3) * 257 + tid]);
                u.z = pack_bf(Wc[(q * 8 + 4) * 257 + tid], Wc[(q * 8 + 5) * 257 + tid]);
                u.w = pack_bf(Wc[(q * 8 + 6) * 257 + tid], Wc[(q * 8 + 7) * 257 + tid]);
                *(uint4*)(dst + q * 16) = u;
            }
        }
    } else {
        if (tid >= 256) {
            // mean@W partial over this k-block: thread = column n
            const int n = tid - 256;
            float a = 0.f;
#pragma unroll 8
            for (int r = 0; r < 32; r++)
                a = fmaf(mean[k0 + r], Wc[r * 257 + n], a);
            g_part[kc32 * NPROJ + n] = a;
        }
    }

    // T-part: thread -> (k = tid&31, c-group cq = (tid>>5)&7, j-half jh = tid>>8)
    {
        const int kl = tid & 31, cq = (tid >> 5) & 7, jh = tid >> 8;
        float acc[4] = {0.f, 0.f, 0.f, 0.f};
        const float* wrow = Wc + kl * 257 + jh * 128;
        const float* prow = Pc + jh * 128;
#pragma unroll 4
        for (int j = 0; j < 128; j++) {
            const float w = wrow[j];
#pragma unroll
            for (int i = 0; i < 4; i++)
                acc[i] = fmaf(w, prow[(cq * 4 + i) * 257 + j], acc[i]);
        }
#pragma unroll
        for (int i = 0; i < 4; i++)
            sT[jh * 1024 + kl * 32 + cq * 4 + i] = acc[i];
    }
    __syncthreads();

    if (tid < 256) {
        const int kl = tid & 31, cq = tid >> 5;
#pragma unroll
        for (int i = 0; i < 4; i++) {
            const int c = c0 + cq * 4 + i;
            const float v = sT[kl * 32 + cq * 4 + i] + sT[1024 + kl * 32 + cq * 4 + i];
            *(__nv_bfloat16*)(cbase + (NPROJ + c) * 128 + (kbase + kl) * 2) =
                __float2bfloat16_rn(v);
        }
    }

    // ---- last block: mproj reduce + mproj@P^T + |P|^2 ----
    __syncthreads();
    if (tid == 0) {
        __threadfence();
        s_last = (atomicAdd(&g_ctr, 1) == 63);
    }
    __syncthreads();
    if (!s_last) return;

    float* sP  = sprep;          // [64][257] (reuses staging region exactly)
    float* sm  = sT;             // [256] mproj
    float* smp = sT + 256;       // [8][64]
    float* sp2 = sT + 768;       // [8][64]

    for (int idx = tid; idx < 4096; idx += PREP_THREADS) {
        const int r = idx >> 6, j4 = (idx & 63) * 4;
        float4 p = *(const float4*)(P + (size_t)r * NPROJ + j4);
        sP[r * 257 + j4 + 0] = p.x; sP[r * 257 + j4 + 1] = p.y;
        sP[r * 257 + j4 + 2] = p.z; sP[r * 257 + j4 + 3] = p.w;
    }
    if (tid < 256) {
        float a = 0.f;
#pragma unroll 8
        for (int b = 0; b < 32; b++) a += g_part[b * NPROJ + tid];
        g_mproj[tid] = a;
        sm[tid] = a;
    }
    __syncthreads();

    // dots: thread -> (c = tid&63, eighth q = tid>>6); 32-j partials
    {
        const int c = tid & 63, q = tid >> 6;
        const float* pr = sP + c * 257 + q * 32;
        const float* mr = sm + q * 32;
        float mp = 0.f, p2 = 0.f;
#pragma unroll 8
        for (int j = 0; j < 32; j++) {
            const float pv = pr[j];
            mp = fmaf(mr[j], pv, mp);
            p2 = fmaf(pv, pv, p2);
        }
        smp[q * 64 + c] = mp;
        sp2[q * 64 + c] = p2;
    }
    __syncthreads();

    if (tid < NC) {
        float mp = 0.f, p2 = 0.f;
#pragma unroll
        for (int q = 0; q < 8; q++) { mp += smp[q * 64 + tid]; p2 += sp2[q * 64 + tid]; }
        g_mpP[tid] = mp;
        g_pn2[tid] = p2;
    }
    if (tid == 0) g_ctr = 0;   // reset for next graph replay
}

// ---------------- main fused GEMM + epilogue ----------------
// grid = nrows/64 CTAs of 256 threads; 2 CTAs/SM. 8 warps = 2(M) x 4(N),
// warp tile 32x80. 16 K-chunks of 64; one barrier per chunk; B double-buffered
// cp.async issued AFTER __syncthreads (all warps past the previous chunk's
// MMAs -> no stage overwrite race); A double-buffered through registers;
// B fragments prefetched one p-step ahead inside the MMA loop.
__global__ __launch_bounds__(THREADS, 2)
void proto_main(const float* __restrict__ X, float* __restrict__ out) {
    extern __shared__ char smem[];
    float* s_ssq   = (float*)(smem + SM_SSQ);
    float* s_mproj = (float*)(smem + SM_MPROJ);
    float* s_mpp   = (float*)(smem + SM_MPP);
    float* s_pn2   = (float*)(smem + SM_PN2);
    const uint32_t sbase = smem_u32(smem);
    const uint32_t sA = sbase + SM_A;
    const uint32_t sB = sbase + SM_B;

    const int tid = threadIdx.x;
    const int lane = tid & 31, wid = tid >> 5;
    const int wm = wid >> 2, wn = wid & 3;
    const int m0 = blockIdx.x * TILE_M;

    for (int i = tid; i < NOUT; i += THREADS)
        s_mproj[i] = (i < NPROJ) ? g_mproj[i] : 0.f;
    if (tid < NC) { s_mpp[tid] = g_mpP[tid]; s_pn2[tid] = g_pn2[tid]; }
    if (tid < TILE_M) s_ssq[tid] = 0.f;

    // A mapping: thread -> (row = tid/4, quarter = tid%4); each thread owns
    // 16 consecutive k of its row per chunk (64B src fp32 -> 32B bf16).
    const int arow = tid >> 2, aq = tid & 3;
    const float* xptr = X + (size_t)(m0 + arow) * DIN + aq * 16;
    char* aStsBase = smem + SM_A + arow * ROWB + aq * 32;

    float acc[2][5][2][4];
#pragma unroll
    for (int mt = 0; mt < 2; mt++)
#pragma unroll
        for (int p = 0; p < 5; p++)
#pragma unroll
            for (int nt = 0; nt < 2; nt++)
#pragma unroll
                for (int q = 0; q < 4; q++) acc[mt][p][nt][q] = 0.f;

    auto loadA = [&](int kc, uint4* dst) {
#pragma unroll
        for (int h = 0; h < 2; h++) {
            float4 v0 = *(const float4*)(xptr + kc * KC + h * 8);
            float4 v1 = *(const float4*)(xptr + kc * KC + h * 8 + 4);
            dst[h].x = pack_bf(v0.x, v0.y);
            dst[h].y = pack_bf(v0.z, v0.w);
            dst[h].z = pack_bf(v1.x, v1.y);
            dst[h].w = pack_bf(v1.z, v1.w);
        }
    };
    auto issueB = [&](int kc, int st) {
        const char* src = (const char*)g_Bimg + (size_t)kc * B_CHUNK_BYTES;
        const uint32_t dstb = sB + st * B_STAGE;
#pragma unroll
        for (int it = 0; it < 10; it++) {
            const int i = tid + it * THREADS;
            const int n = i >> 3, ch = i & 7;
            CP_ASYNC16(dstb + n * ROWB + ch * 16, src + n * 128 + ch * 16);
        }
        CP_COMMIT();
    };

    // ---- prologue ----
    issueB(0, 0);
    uint4 aCur[2], aNxt[2];
    loadA(0, aCur);

    // ldmatrix address invariants
    const uint32_t aRow = wm * 32 + (lane & 15);
    const uint32_t aColHalf = (lane >> 4) * 16;
    const uint32_t bRowOff = (lane & 7) + ((lane >> 4) & 1) * 8;
    const uint32_t bColHalf = ((lane >> 3) & 1) * 16;

    for (int kc = 0; kc < NKCH; kc++) {
        const int st = kc & 1;
        *(uint4*)(aStsBase + st * A_STAGE)      = aCur[0];
        *(uint4*)(aStsBase + st * A_STAGE + 16) = aCur[1];
        if (kc < NKCH - 1) loadA(kc + 1, aNxt);

        asm volatile("cp.async.wait_group 0;" ::: "memory");
        __syncthreads();
        if (kc < NKCH - 1) issueB(kc + 1, st ^ 1);

        const uint32_t aBase = sA + st * A_STAGE;
        const uint32_t bBase = sB + st * B_STAGE;
#pragma unroll
        for (int ks = 0; ks < 4; ks++) {
            uint32_t af[2][4];
#pragma unroll
            for (int mt = 0; mt < 2; mt++) {
                const uint32_t addr = aBase + (aRow + mt * 16) * ROWB + ks * 32 + aColHalf;
                LDSM_X4(af[mt][0], af[mt][1], af[mt][2], af[mt][3], addr);
            }
            const uint32_t bks = bBase + ks * 32 + bColHalf + bRowOff * ROWB + wn * (80 * ROWB);
            uint32_t bq[4], bn[4];
            LDSM_X4(bq[0], bq[1], bq[2], bq[3], bks);
#pragma unroll
            for (int p = 0; p < 5; p++) {
                if (p < 4) LDSM_X4(bn[0], bn[1], bn[2], bn[3], bks + (p + 1) * (16 * ROWB));
#pragma unroll
                for (int mt = 0; mt < 2; mt++) {
                    mma16816(acc[mt][p][0], af[mt], bq[0], bq[1]);
                    mma16816(acc[mt][p][1], af[mt], bq[2], bq[3]);
                }
                bq[0] = bn[0]; bq[1] = bn[1]; bq[2] = bn[2]; bq[3] = bn[3];
            }
        }
        aCur[0] = aNxt[0]; aCur[1] = aNxt[1];
    }

    // ---------------- epilogue ----------------
    // 1) partial sumsq of centered Z per row (cols >= 256 gated to 0)
    float pss[2][2] = {{0.f, 0.f}, {0.f, 0.f}};
#pragma unroll
    for (int mt = 0; mt < 2; mt++)
#pragma unroll
        for (int p = 0; p < 5; p++)
#pragma unroll
            for (int nt = 0; nt < 2; nt++) {
                const int col = wn * 80 + p * 16 + nt * 8 + (lane & 3) * 2;
                const float g = (col < NPROJ) ? 1.f : 0.f;
                const float mv0 = s_mproj[col], mv1 = s_mproj[col + 1];
                float v0 = acc[mt][p][nt][0] - mv0;
                float v1 = acc[mt][p][nt][1] - mv1;
                float v2 = acc[mt][p][nt][2] - mv0;
                float v3 = acc[mt][p][nt][3] - mv1;
                pss[mt][0] += g * fmaf(v0, v0, v1 * v1);
                pss[mt][1] += g * fmaf(v2, v2, v3 * v3);
            }
#pragma unroll
    for (int mt = 0; mt < 2; mt++)
#pragma unroll
        for (int rh = 0; rh < 2; rh++) {
            float v = pss[mt][rh];
            v += __shfl_xor_sync(0xFFFFFFFFu, v, 1);
            v += __shfl_xor_sync(0xFFFFFFFFu, v, 2);
            if ((lane & 3) == 0)
                atomicAdd(&s_ssq[wm * 32 + mt * 16 + rh * 8 + (lane >> 2)], v);
        }
    __syncthreads();

    // 2) scores: wn==3 warps hold all T columns (256..319)
    if (wn == 3) {
#pragma unroll
        for (int mt = 0; mt < 2; mt++) {
            const int rbase = wm * 32 + mt * 16 + (lane >> 2);
            float rn[2];
#pragma unroll
            for (int rh = 0; rh < 2; rh++) {
                const float ss = s_ssq[rbase + rh * 8];
                rn[rh] = 1.f / fmaxf(sqrtf(ss), 1e-12f);
            }
#pragma unroll
            for (int p = 1; p < 5; p++)
#pragma unroll
                for (int nt = 0; nt < 2; nt++) {
                    const int c = p * 16 + nt * 8 + (lane & 3) * 2 - 16;  // 0..62
                    const float mp0 = s_mpp[c], mp1 = s_mpp[c + 1];
                    const float pn0 = s_pn2[c], pn1 = s_pn2[c + 1];
#pragma unroll
                    for (int rh = 0; rh < 2; rh++) {
                        const float s0 = (acc[mt][p][nt][rh * 2 + 0] - mp0) * rn[rh];
                        const float s1 = (acc[mt][p][nt][rh * 2 + 1] - mp1) * rn[rh];
                        float2 o;
                        o.x = -sqrtf(fmaxf(fmaf(-2.f, s0, 1.f + pn0), 0.f));
                        o.y = -sqrtf(fmaxf(fmaf(-2.f, s1, 1.f + pn1), 0.f));
                        const int row = m0 + rbase + rh * 8;
                        *(float2*)(out + (size_t)row * NC + c) = o;
                    }
                }
        }
    }
}

// ---------------- launch ----------------
extern "C" void kernel_launch(void* const* d_in, const int* in_sizes, int n_in,
                              void* d_out, int out_size) {
    const float* X    = (const float*)d_in[0];   // [8,2048,1024]
    const float* P    = (const float*)d_in[1];   // [64,256]
    const float* mean = (const float*)d_in[2];   // [1024]
    const float* W    = (const float*)d_in[3];   // [1024,256]
    float* out = (float*)d_out;                  // [8,2048,64]

    const int nrows = in_sizes[0] / DIN;         // 16384

    cudaFuncSetAttribute(proto_main, cudaFuncAttributeMaxDynamicSharedMemorySize, SM_TOTAL);
    cudaFuncSetAttribute(prep_img, cudaFuncAttributeMaxDynamicSharedMemorySize, PREP_SMEM_BYTES);

    prep_img<<<64, PREP_THREADS, PREP_SMEM_BYTES>>>(W, P, mean);
    proto_main<<<nrows / TILE_M, THREADS, SM_TOTAL>>>(X, out);
}